// round 4
// baseline (speedup 1.0000x reference)
#include <cuda_runtime.h>
#include <cuda_fp16.h>

// SinkhornDistance: B=64, N=M=1024, eps=0.1, 50 iterations.
// Scaling domain: K = exp(-C/eps); a = (mu+1e-8)/(K b); b = (nu+1e-8)/(K^T a)
// pi = exp(-C/eps) * a_i * b_j (fp32, on the fly) ; cost_b = sum pi*C.
//
// R4: latency-restructured fused iteration:
//  - all 16 rows of the K tile loaded up-front (ONE L2 latency exposure/block)
//  - mu prefetched to smem at block start; fast divide -> tiny critical section
//  - 2 barriers per block (was 5)

#define BATCH 64
#define NN 1024
#define INV_EPS 10.0f
#define LOGEPS 1e-8f
#define MAX_ITER 50
#define EXP10 22026.4657948f  // exp(1/eps) -> b for v0 = 1

#define GSZ 32               // batches per group (2 groups)
#define RPB 16               // rows per block
#define BPB (NN / RPB)       // 64 blocks per batch

// Scratch (static device globals; no runtime allocation)
__device__ __half g_K16[(size_t)BATCH * NN * NN];  // 128 MB
__device__ float g_a[BATCH * NN];
__device__ float g_T[3][BATCH * NN];               // rotation buffers

// ---------------------------------------------------------------------------
// K16 = fp16(exp(-C/eps)) for one group's slab. Thread handles 4 elements.
__global__ void __launch_bounds__(256) k_precompute16(const float* __restrict__ C,
                                                      int group_start) {
    size_t base = (size_t)group_start * NN * NN;
    size_t i = base + ((size_t)blockIdx.x * 256 + threadIdx.x) * 4;
    float4 c = *(const float4*)(C + i);
    __half2 h0 = __floats2half2_rn(__expf(-c.x * INV_EPS), __expf(-c.y * INV_EPS));
    __half2 h1 = __floats2half2_rn(__expf(-c.z * INV_EPS), __expf(-c.w * INV_EPS));
    uint2 pk;
    pk.x = *(const unsigned int*)&h0;
    pk.y = *(const unsigned int*)&h1;
    *(uint2*)(g_K16 + i) = pk;
}

// Zero cost[64] and T[0] for all batches. grid = 64 blocks x 256 threads.
__global__ void k_init(float* __restrict__ cost) {
    int idx = blockIdx.x * 256 + threadIdx.x;  // 16384 float4 = 64K floats
    ((float4*)g_T[0])[idx] = make_float4(0.f, 0.f, 0.f, 0.f);
    if (blockIdx.x == 0 && threadIdx.x < BATCH) cost[threadIdx.x] = 0.0f;
}

// ---------------------------------------------------------------------------
// Fused iteration on fp16 K. Block owns 16 rows of one batch; thread owns 4
// columns. Whole 16-row tile loaded into regs up front; K read exactly once.
// Buffers: read T[(it+2)%3], write T[it%3], zero-ahead T[(it+1)%3].
__global__ void __launch_bounds__(256) fused_iter(
    const float* __restrict__ mu, const float* __restrict__ nu,
    int group_start, int iter)
{
    int batch = group_start + blockIdx.x / BPB;
    int r0 = (blockIdx.x % BPB) * RPB;
    int tid = threadIdx.x;
    int lane = tid & 31, warp = tid >> 5;

    __shared__ float mush[RPB];
    __shared__ float wsum[RPB][8];
    __shared__ float ash[RPB];

    // Prefetch mu for this block's rows (retires while phase 1 runs).
    if (tid < RPB) mush[tid] = mu[(size_t)batch * NN + r0 + tid];

    // b at this thread's 4 columns
    float4 bv;
    if (iter == 0) {
        bv = make_float4(EXP10, EXP10, EXP10, EXP10);
    } else {
        float4 t = ((const float4*)&g_T[(iter + 2) % 3][(size_t)batch * NN])[tid];
        float4 n = ((const float4*)(nu + (size_t)batch * NN))[tid];
        bv.x = __fdividef(n.x + LOGEPS, t.x);
        bv.y = __fdividef(n.y + LOGEPS, t.y);
        bv.z = __fdividef(n.z + LOGEPS, t.z);
        bv.w = __fdividef(n.w + LOGEPS, t.w);
    }

    // Zero-ahead: buffer (iter+1)%3 is untouched by all other blocks this
    // launch (last read was in the previous launch) -> race-free.
    if ((blockIdx.x % BPB) == 0) {
        ((float4*)&g_T[(iter + 1) % 3][(size_t)batch * NN])[tid] =
            make_float4(0.f, 0.f, 0.f, 0.f);
    }

    const uint2* __restrict__ Kb =
        (const uint2*)(g_K16 + (size_t)batch * NN * NN);

    // Load ALL 16 rows up front: single L2 latency exposure.
    uint2 kv[RPB];
#pragma unroll
    for (int r = 0; r < RPB; r++)
        kv[r] = Kb[(size_t)(r0 + r) * (NN / 4) + tid];

    // Phase 1: row dots + warp reduce (no barrier until all rows done).
#pragma unroll
    for (int r = 0; r < RPB; r++) {
        float2 f01 = __half22float2(*(__half2*)&kv[r].x);
        float2 f23 = __half22float2(*(__half2*)&kv[r].y);
        float s = f01.x * bv.x + f01.y * bv.y + f23.x * bv.z + f23.y * bv.w;
#pragma unroll
        for (int o = 16; o; o >>= 1) s += __shfl_xor_sync(0xffffffffu, s, o);
        if (lane == 0) wsum[r][warp] = s;
    }
    __syncthreads();

    // Tiny critical section: smem-only + fast divide.
    if (tid < RPB) {
        float s = 0.f;
#pragma unroll
        for (int w = 0; w < 8; w++) s += wsum[tid][w];
        float a = __fdividef(mush[tid] + LOGEPS, s);
        ash[tid] = a;
        if (iter == MAX_ITER - 1) g_a[(size_t)batch * NN + r0 + tid] = a;
    }
    __syncthreads();

    // Phase 2: column partials from the register-resident tile.
    float4 acc = make_float4(0.f, 0.f, 0.f, 0.f);
#pragma unroll
    for (int r = 0; r < RPB; r++) {
        float a = ash[r];
        float2 f01 = __half22float2(*(__half2*)&kv[r].x);
        float2 f23 = __half22float2(*(__half2*)&kv[r].y);
        acc.x += f01.x * a;
        acc.y += f01.y * a;
        acc.z += f23.x * a;
        acc.w += f23.y * a;
    }

    float* T = &g_T[iter % 3][(size_t)batch * NN] + tid * 4;
    atomicAdd(T + 0, acc.x);
    atomicAdd(T + 1, acc.y);
    atomicAdd(T + 2, acc.z);
    atomicAdd(T + 3, acc.w);
}

// ---------------------------------------------------------------------------
// Epilogue (per group): read C (fp32), K = exp(-C/eps) on the fly,
// pi = K*a_i*b_j (fp32), cost_b += sum pi*C. Final T buffer: (MAX_ITER-1)%3.
__global__ void __launch_bounds__(256) epilogue(
    const float* __restrict__ C, const float* __restrict__ nu,
    float* __restrict__ out_cost, float* __restrict__ out_pi, int group_start)
{
    __shared__ float bsh[NN];
    const int blocksPerBatch = NN / 8;
    int batch = group_start + blockIdx.x / blocksPerBatch;
    int rowBase = (blockIdx.x % blocksPerBatch) * 8;
    int tid = threadIdx.x;

    const float* __restrict__ T = &g_T[(MAX_ITER - 1) % 3][(size_t)batch * NN];
    for (int j = tid; j < NN; j += 256)
        bsh[j] = (nu[(size_t)batch * NN + j] + LOGEPS) / T[j];
    __syncthreads();

    int warp = tid >> 5, lane = tid & 31;
    int row = rowBase + warp;
    float a = g_a[(size_t)batch * NN + row];
    const float4* __restrict__ Crow =
        (const float4*)(C + ((size_t)batch * NN + row) * NN);
    float4* __restrict__ Prow =
        (float4*)(out_pi + ((size_t)batch * NN + row) * NN);
    const float4* __restrict__ bsh4 = (const float4*)bsh;

    float cacc = 0.0f;
#pragma unroll
    for (int k = 0; k < 8; k++) {
        int idx = k * 32 + lane;
        float4 cv = Crow[idx];
        float4 bv = bsh4[idx];
        float4 p;
        p.x = __expf(-cv.x * INV_EPS) * a * bv.x;
        p.y = __expf(-cv.y * INV_EPS) * a * bv.y;
        p.z = __expf(-cv.z * INV_EPS) * a * bv.z;
        p.w = __expf(-cv.w * INV_EPS) * a * bv.w;
        cacc += p.x * cv.x + p.y * cv.y + p.z * cv.z + p.w * cv.w;
        Prow[idx] = p;
    }
#pragma unroll
    for (int o = 16; o; o >>= 1) cacc += __shfl_xor_sync(0xffffffffu, cacc, o);
    if (lane == 0) atomicAdd(&out_cost[batch], cacc);
}

// ---------------------------------------------------------------------------
extern "C" void kernel_launch(void* const* d_in, const int* in_sizes, int n_in,
                              void* d_out, int out_size) {
    const float* mu = (const float*)d_in[0];
    const float* nu = (const float*)d_in[1];
    const float* C  = (const float*)d_in[2];
    float* cost = (float*)d_out;                 // outputs: (cost[64], pi[64M])
    float* pi   = (float*)d_out + BATCH;

    k_init<<<64, 256>>>(cost);

    const int precompBlocks = GSZ * NN * NN / (256 * 4);  // 32768
    for (int g = 0; g < BATCH / GSZ; g++) {
        int start = g * GSZ;
        k_precompute16<<<precompBlocks, 256>>>(C, start);
        for (int it = 0; it < MAX_ITER; it++) {
            fused_iter<<<GSZ * BPB, 256>>>(mu, nu, start, it);
        }
        epilogue<<<GSZ * (NN / 8), 256>>>(C, nu, cost, pi, start);
    }
}